// round 7
// baseline (speedup 1.0000x reference)
#include <cuda_runtime.h>
#include <cuda_fp16.h>
#include <cstdint>

// ---------------------------------------------------------------------------
// Problem constants
// ---------------------------------------------------------------------------
#define N_IMG  16
#define CI     256
#define CO     256
#define HW     56
#define KTAP   13
#define PAD    6
#define HP     68           // 56 + 12
#define WPAD   76           // 56 + 12 padding + slack

// Scratch (device globals; no cudaMalloc allowed)
__device__ __half g_xp[(size_t)N_IMG * HP * WPAD * CI];     // [n][hp][wp][ci]  ~42 MB
__device__ __half g_wt[(size_t)KTAP * KTAP * CO * CI];      // [tap][co][ci]    ~22 MB

// ---------------------------------------------------------------------------
// Helpers (arch-neutral PTX: mma.sync / ldmatrix / cp.async)
// ---------------------------------------------------------------------------
__device__ __forceinline__ uint32_t smem_u32(const void* p) {
    uint32_t a;
    asm("{ .reg .u64 t; cvta.to.shared.u64 t, %1; cvt.u32.u64 %0, t; }" : "=r"(a) : "l"(p));
    return a;
}
__device__ __forceinline__ uint32_t swz(uint32_t off) {      // SW128: bits[4:6] ^= bits[7:9]
    return off ^ ((off >> 3) & 0x70);
}
__device__ __forceinline__ void cp16(uint32_t dst, const void* src) {
    asm volatile("cp.async.cg.shared.global [%0], [%1], 16;" :: "r"(dst), "l"(src) : "memory");
}
#define CP_COMMIT() asm volatile("cp.async.commit_group;" ::: "memory")
#define CP_WAIT(n)  asm volatile("cp.async.wait_group %0;" :: "n"(n) : "memory")

__device__ __forceinline__ void ldsm4(uint32_t* r, uint32_t addr) {
    asm volatile("ldmatrix.sync.aligned.m8n8.x4.shared.b16 {%0,%1,%2,%3}, [%4];"
                 : "=r"(r[0]), "=r"(r[1]), "=r"(r[2]), "=r"(r[3]) : "r"(addr));
}
__device__ __forceinline__ void ldsm2(uint32_t* r, uint32_t addr) {
    asm volatile("ldmatrix.sync.aligned.m8n8.x2.shared.b16 {%0,%1}, [%2];"
                 : "=r"(r[0]), "=r"(r[1]) : "r"(addr));
}
__device__ __forceinline__ void mma16816(float* d, const uint32_t* a, const uint32_t* b) {
    asm volatile(
        "mma.sync.aligned.m16n8k16.row.col.f32.f16.f16.f32 "
        "{%0,%1,%2,%3}, {%4,%5,%6,%7}, {%8,%9}, {%0,%1,%2,%3};"
        : "+f"(d[0]), "+f"(d[1]), "+f"(d[2]), "+f"(d[3])
        : "r"(a[0]), "r"(a[1]), "r"(a[2]), "r"(a[3]), "r"(b[0]), "r"(b[1]));
}

// ---------------------------------------------------------------------------
// Fused prepass: blocks [0, N_IMG*HP) pad+transpose input; the rest transpose
// weights. Both branches 256 threads; one launch so the two overlap.
// ---------------------------------------------------------------------------
#define PAD_BLOCKS (N_IMG * HP)          // 1088
#define WT_BLOCKS  (CO * KTAP)           // 3328
#define SROW 57                          // f16 tile row pitch (56 + 1)
#define WSROW 258                        // weight smem tap-row pitch

__global__ void __launch_bounds__(256) prep_kernel(
    const float* __restrict__ x, const float* __restrict__ w)
{
    __shared__ __half s[256 * SROW];     // 29.2 KB (weight branch reuses prefix)
    const int bx  = blockIdx.x;
    const int tid = threadIdx.x;

    if (bx < PAD_BLOCKS) {
        // ---- pad branch: one (n, hp) row
        const int n  = bx / HP;
        const int hp = bx % HP;
        const int h  = hp - PAD;
        const bool hv = (h >= 0) && (h < HW);
        // Phase 1: coalesced reads along w. Threads = (w:64) x (ci:4).
        const int wq = tid & 63, cq = tid >> 6;
        if (hv && wq < HW) {
            const float* xr = x + ((size_t)(n * CI + cq) * HW + h) * HW + wq;
            #pragma unroll 8
            for (int c0 = 0; c0 < CI; c0 += 4)
                s[(c0 + cq) * SROW + wq] = __float2half(xr[(size_t)c0 * HW * HW]);
        }
        __syncthreads();
        // Phase 2: coalesced half2 stores. Threads = (ci-pair:128) x (wp-phase:2).
        const int cp2 = tid & 127;
        const int wo  = tid >> 7;
        __half2* dst = (__half2*)(g_xp + ((size_t)(n * HP + hp) * WPAD) * CI) + cp2;
        const __half* s0 = s + (2 * cp2) * SROW;
        const __half* s1 = s + (2 * cp2 + 1) * SROW;
        #pragma unroll
        for (int k = 0; k < WPAD / 2; ++k) {
            const int wp = wo + 2 * k;
            const int ww = wp - PAD;
            __half2 v = __half2half2(__float2half(0.f));
            if (hv && ww >= 0 && ww < HW) v = __halves2half2(s0[ww], s1[ww]);
            dst[(size_t)wp * (CI / 2)] = v;
        }
    } else {
        // ---- weight branch: one (co, tap-row); smem transpose
        const int idx = bx - PAD_BLOCKS;
        const int co = idx / KTAP;
        const int kr = idx - co * KTAP;
        const float* src = w + ((size_t)co * CI) * (KTAP * KTAP) + kr * KTAP;
        // fill: 3328 elems, j = ci*13 + tap (contiguous 13-float runs per ci)
        #pragma unroll
        for (int k = 0; k < 13; ++k) {
            const int j  = tid + k * 256;
            const int ci = j / 13;
            const int tp = j - ci * 13;
            s[tp * WSROW + ci] = __float2half(src[(size_t)ci * (KTAP * KTAP) + tp]);
        }
        __syncthreads();
        // drain: per tap, 256 coalesced half stores (threads = ci)
        __half* dst = g_wt + (size_t)(kr * KTAP) * (CO * CI) + (size_t)co * CI + tid;
        #pragma unroll
        for (int tp = 0; tp < 13; ++tp)
            dst[(size_t)tp * (CO * CI)] = s[tp * WSROW + tid];
    }
}

// ---------------------------------------------------------------------------
// Main: implicit-GEMM conv + BN + SiLU via mma.sync (m16n8k16 f16->f32)
// CTA: 128 threads (4 warps 2x2), tile M=128 co x N=112 spatial
// Warp tile 64(M) x 56(N); K loop 676 iters, 3-stage cp.async pipeline,
// one barrier per iter; A fragments register-double-buffered across kk.
// grid = (448, 2)
// ---------------------------------------------------------------------------
#define A_BYTES     16384          // 128 rows x 128B
#define B_BYTES     14336          // 112 rows x 128B
#define STAGE_BYTES (A_BYTES + B_BYTES)     // 30720
#define NSTAGE      3
#define SMEM_DYN    (NSTAGE * STAGE_BYTES + 1024)

__global__ void __launch_bounds__(128, 2) conv_main_kernel(
    const float* __restrict__ gamma, const float* __restrict__ beta,
    const float* __restrict__ rmean, const float* __restrict__ rvar,
    float* __restrict__ out)
{
    extern __shared__ char smem_raw[];
    const uint32_t base = (smem_u32(smem_raw) + 1023u) & ~1023u;

    const int tid = threadIdx.x;
    const int l   = tid & 31;
    const int wid = tid >> 5;
    const int st  = blockIdx.x;
    const int cob = blockIdx.y;
    const int n   = st / 28;
    const int h0  = (st % 28) * 2;

    // ---- cp.async geometry: 8x16B chunks per 128B row; 128 thr = 16 rows/pass
    const int c16  = tid & 7;
    const int row0 = tid >> 3;                 // 0..15
    const char* a_base = (const char*)g_wt
        + (size_t)(cob * 128 + row0) * (CI * 2) + c16 * 16;
    const uint32_t a_dst0 = swz((uint32_t)(row0 * 128 + c16 * 16));
    const char* b_base = (const char*)g_xp
        + (size_t)(n * HP + h0) * WPAD * (CI * 2) + c16 * 16;
    uint32_t b_off[7];
    #pragma unroll
    for (int i = 0; i < 7; ++i) {
        const int rj = row0 + 16 * i;
        const int jr = (rj >= 56);
        b_off[i] = (uint32_t)(rj + jr * (WPAD - 56)) * (CI * 2);
    }
    const uint32_t b_dst0 = swz((uint32_t)(row0 * 128 + c16 * 16)) + A_BYTES;

    // Producer counters (no division in loop)
    int p_kc = 0;
    size_t p_woff = 0;
    size_t p_xoff = 0;
    int p_s = 0;
    int p_ws = 0;

    auto issue = [&]() {
        const uint32_t sb = base + (uint32_t)p_ws * STAGE_BYTES;
        const char* asrc = a_base + p_woff + (size_t)p_kc * 128;
        const char* bsrc = b_base + p_xoff + (size_t)p_kc * 128;
        #pragma unroll
        for (int i = 0; i < 8; ++i)
            cp16(sb + a_dst0 + i * 2048u, asrc + (size_t)i * 16 * (CI * 2));
        #pragma unroll
        for (int i = 0; i < 7; ++i)
            cp16(sb + b_dst0 + i * 2048u, bsrc + b_off[i]);
        CP_COMMIT();
        if (++p_ws == NSTAGE) p_ws = 0;
        if (++p_kc == 4) {
            p_kc = 0;
            p_woff += (size_t)CO * CI * 2;
            if (++p_s == KTAP) { p_s = 0; p_xoff += (size_t)(WPAD - (KTAP - 1)) * CI * 2; }
            else               { p_xoff += (size_t)CI * 2; }
        }
    };

    // ---- MMA fragment geometry (warp grid 2x2, warp tile 64(M) x 56(N))
    const int wm = wid >> 1, wn = wid & 1;
    const int m0 = wm * 64, n0 = wn * 56;
    uint32_t arow[4], axor[4];
    int brow[3]; uint32_t bxor[3];
    const uint32_t hi_a = (uint32_t)((l >> 4) << 4);
    const uint32_t hi_b = (uint32_t)(((l >> 3) & 1) << 4);
    #pragma unroll
    for (int mt = 0; mt < 4; ++mt) {
        const int r = m0 + 16 * mt + (l & 15);
        arow[mt] = (uint32_t)(r * 128);
        axor[mt] = (uint32_t)((r & 7) << 4);
    }
    #pragma unroll
    for (int bt = 0; bt < 3; ++bt) {
        const int r = n0 + 16 * bt + (l & 7) + ((l >> 4) << 3);
        brow[bt] = r; bxor[bt] = (uint32_t)((r & 7) << 4);
    }
    const int lm = l & 15;
    const int trow = n0 + 48 + (lm & 7);
    const uint32_t txor = (uint32_t)((trow & 7) << 4);
    const uint32_t thi  = (uint32_t)(((lm >> 3) & 1) << 4);

    float acc[4][7][4];
    #pragma unroll
    for (int i = 0; i < 4; ++i)
        #pragma unroll
        for (int j = 0; j < 7; ++j)
            #pragma unroll
            for (int k = 0; k < 4; ++k) acc[i][j][k] = 0.f;

    auto compute = [&](int stage) {
        const uint32_t ab = base + (uint32_t)stage * STAGE_BYTES;
        const uint32_t bb = ab + A_BYTES;
        uint32_t a[2][4][4];
        #pragma unroll
        for (int mt = 0; mt < 4; ++mt)
            ldsm4(a[0][mt], ab + arow[mt] + (hi_a ^ axor[mt]));
        #pragma unroll
        for (int kk = 0; kk < 4; ++kk) {
            const int cur = kk & 1;
            if (kk < 3) {
                #pragma unroll
                for (int mt = 0; mt < 4; ++mt)
                    ldsm4(a[cur ^ 1][mt],
                          ab + arow[mt] + (((uint32_t)(kk + 1) * 32 + hi_a) ^ axor[mt]));
            }
            #pragma unroll
            for (int bt = 0; bt < 3; ++bt) {
                uint32_t b[4];
                ldsm4(b, bb + brow[bt] * 128 + (((uint32_t)kk * 32 + hi_b) ^ bxor[bt]));
                #pragma unroll
                for (int mt = 0; mt < 4; ++mt) {
                    mma16816(acc[mt][2 * bt],     a[cur][mt], b);
                    mma16816(acc[mt][2 * bt + 1], a[cur][mt], b + 2);
                }
            }
            {   // tail 8 N-rows (one mma B operand)
                uint32_t b[2];
                ldsm2(b, bb + trow * 128 + (((uint32_t)kk * 32 + thi) ^ txor));
                #pragma unroll
                for (int mt = 0; mt < 4; ++mt)
                    mma16816(acc[mt][6], a[cur][mt], b);
            }
        }
    };

    // ---- mainloop: 676 K-stages, 3-stage pipeline, one barrier per iter.
    issue();   // stage 0
    issue();   // stage 1
    int rs = 0;
    #pragma unroll 1
    for (int i = 0; i < 674; ++i) {
        CP_WAIT(1);
        __syncthreads();
        issue();                   // iter i+2 -> stage (i+2)%3
        compute(rs);
        if (++rs == NSTAGE) rs = 0;
    }
    CP_WAIT(0);
    __syncthreads();
    compute(rs); if (++rs == NSTAGE) rs = 0;
    compute(rs);

    // ---- epilogue: BN + SiLU, registers -> NCHW fp32 (all lanes valid)
    const int h = h0 + wn;
    #pragma unroll
    for (int mt = 0; mt < 4; ++mt) {
        #pragma unroll
        for (int hf = 0; hf < 2; ++hf) {
            const int co = cob * 128 + m0 + 16 * mt + 8 * hf + (l >> 2);
            const float sc = gamma[co] * rsqrtf(rvar[co] + 1e-5f);
            const float sh = beta[co] - rmean[co] * sc;
            float* op = out + ((size_t)(n * CO + co) * HW + h) * HW;
            #pragma unroll
            for (int nt = 0; nt < 7; ++nt) {
                #pragma unroll
                for (int e = 0; e < 2; ++e) {
                    const int w = 8 * nt + 2 * (l & 3) + e;
                    const float y = acc[mt][nt][hf * 2 + e] * sc + sh;
                    op[w] = y / (1.f + __expf(-y));
                }
            }
        }
    }
}

// ---------------------------------------------------------------------------
// kernel_launch
// ---------------------------------------------------------------------------
extern "C" void kernel_launch(void* const* d_in, const int* in_sizes, int n_in,
                              void* d_out, int out_size)
{
    const float* x     = (const float*)d_in[0];
    const float* w     = (const float*)d_in[1];
    const float* gamma = (const float*)d_in[2];
    const float* beta  = (const float*)d_in[3];
    const float* rmean = (const float*)d_in[4];
    const float* rvar  = (const float*)d_in[5];
    float* out = (float*)d_out;

    cudaFuncSetAttribute(conv_main_kernel,
                         cudaFuncAttributeMaxDynamicSharedMemorySize, SMEM_DYN);

    prep_kernel<<<PAD_BLOCKS + WT_BLOCKS, 256>>>(x, w);
    conv_main_kernel<<<dim3(N_IMG * 28, 2), 128, SMEM_DYN>>>(gamma, beta, rmean, rvar, out);
}

// round 8
// speedup vs baseline: 1.0025x; 1.0025x over previous
#include <cuda_runtime.h>
#include <cuda_fp16.h>
#include <cstdint>

// ---------------------------------------------------------------------------
// Problem constants
// ---------------------------------------------------------------------------
#define N_IMG  16
#define CI     256
#define CO     256
#define HW     56
#define KTAP   13
#define PAD    6
#define HP     68           // 56 + 12
#define WPAD   76           // 56 + 12 padding + slack

// Scratch (device globals; no cudaMalloc allowed)
__device__ __half g_xp[(size_t)N_IMG * HP * WPAD * CI];     // [n][hp][wp][ci]  ~42 MB
__device__ __half g_wt[(size_t)KTAP * KTAP * CO * CI];      // [tap][co][ci]    ~22 MB

// ---------------------------------------------------------------------------
// Helpers (arch-neutral PTX: mma.sync / ldmatrix / cp.async)
// ---------------------------------------------------------------------------
__device__ __forceinline__ uint32_t smem_u32(const void* p) {
    uint32_t a;
    asm("{ .reg .u64 t; cvta.to.shared.u64 t, %1; cvt.u32.u64 %0, t; }" : "=r"(a) : "l"(p));
    return a;
}
__device__ __forceinline__ uint32_t swz(uint32_t off) {      // SW128: bits[4:6] ^= bits[7:9]
    return off ^ ((off >> 3) & 0x70);
}
__device__ __forceinline__ void cp16(uint32_t dst, const void* src) {
    asm volatile("cp.async.cg.shared.global [%0], [%1], 16;" :: "r"(dst), "l"(src) : "memory");
}
#define CP_COMMIT() asm volatile("cp.async.commit_group;" ::: "memory")
#define CP_WAIT(n)  asm volatile("cp.async.wait_group %0;" :: "n"(n) : "memory")

__device__ __forceinline__ void ldsm4(uint32_t* r, uint32_t addr) {
    asm volatile("ldmatrix.sync.aligned.m8n8.x4.shared.b16 {%0,%1,%2,%3}, [%4];"
                 : "=r"(r[0]), "=r"(r[1]), "=r"(r[2]), "=r"(r[3]) : "r"(addr));
}
__device__ __forceinline__ void ldsm2(uint32_t* r, uint32_t addr) {
    asm volatile("ldmatrix.sync.aligned.m8n8.x2.shared.b16 {%0,%1}, [%2];"
                 : "=r"(r[0]), "=r"(r[1]) : "r"(addr));
}
__device__ __forceinline__ void mma16816(float* d, const uint32_t* a, const uint32_t* b) {
    asm volatile(
        "mma.sync.aligned.m16n8k16.row.col.f32.f16.f16.f32 "
        "{%0,%1,%2,%3}, {%4,%5,%6,%7}, {%8,%9}, {%0,%1,%2,%3};"
        : "+f"(d[0]), "+f"(d[1]), "+f"(d[2]), "+f"(d[3])
        : "r"(a[0]), "r"(a[1]), "r"(a[2]), "r"(a[3]), "r"(b[0]), "r"(b[1]));
}

// ---------------------------------------------------------------------------
// Fused prepass: blocks [0, N_IMG*HP) pad+transpose input; the rest transpose
// weights. Both branches 256 threads; one launch so the two overlap.
// ---------------------------------------------------------------------------
#define PAD_BLOCKS (N_IMG * HP)          // 1088
#define WT_BLOCKS  (CO * KTAP)           // 3328
#define SROW 57                          // f16 tile row pitch (56 + 1)
#define WSROW 258                        // weight smem tap-row pitch

__global__ void __launch_bounds__(256) prep_kernel(
    const float* __restrict__ x, const float* __restrict__ w)
{
    __shared__ __half s[256 * SROW];     // 29.2 KB (weight branch reuses prefix)
    const int bx  = blockIdx.x;
    const int tid = threadIdx.x;

    if (bx < PAD_BLOCKS) {
        // ---- pad branch: one (n, hp) row
        const int n  = bx / HP;
        const int hp = bx % HP;
        const int h  = hp - PAD;
        const bool hv = (h >= 0) && (h < HW);
        // Phase 1: coalesced reads along w. Threads = (w:64) x (ci:4).
        const int wq = tid & 63, cq = tid >> 6;
        if (hv && wq < HW) {
            const float* xr = x + ((size_t)(n * CI + cq) * HW + h) * HW + wq;
            #pragma unroll 8
            for (int c0 = 0; c0 < CI; c0 += 4)
                s[(c0 + cq) * SROW + wq] = __float2half(xr[(size_t)c0 * HW * HW]);
        }
        __syncthreads();
        // Phase 2: coalesced half2 stores. Threads = (ci-pair:128) x (wp-phase:2).
        const int cp2 = tid & 127;
        const int wo  = tid >> 7;
        __half2* dst = (__half2*)(g_xp + ((size_t)(n * HP + hp) * WPAD) * CI) + cp2;
        const __half* s0 = s + (2 * cp2) * SROW;
        const __half* s1 = s + (2 * cp2 + 1) * SROW;
        #pragma unroll
        for (int k = 0; k < WPAD / 2; ++k) {
            const int wp = wo + 2 * k;
            const int ww = wp - PAD;
            __half2 v = __half2half2(__float2half(0.f));
            if (hv && ww >= 0 && ww < HW) v = __halves2half2(s0[ww], s1[ww]);
            dst[(size_t)wp * (CI / 2)] = v;
        }
    } else {
        // ---- weight branch: one (co, tap-row); smem transpose
        const int idx = bx - PAD_BLOCKS;
        const int co = idx / KTAP;
        const int kr = idx - co * KTAP;
        const float* src = w + ((size_t)co * CI) * (KTAP * KTAP) + kr * KTAP;
        #pragma unroll
        for (int k = 0; k < 13; ++k) {
            const int j  = tid + k * 256;
            const int ci = j / 13;
            const int tp = j - ci * 13;
            s[tp * WSROW + ci] = __float2half(src[(size_t)ci * (KTAP * KTAP) + tp]);
        }
        __syncthreads();
        __half* dst = g_wt + (size_t)(kr * KTAP) * (CO * CI) + (size_t)co * CI + tid;
        #pragma unroll
        for (int tp = 0; tp < 13; ++tp)
            dst[(size_t)tp * (CO * CI)] = s[tp * WSROW + tid];
    }
}

// ---------------------------------------------------------------------------
// Main: implicit-GEMM conv + BN + SiLU via mma.sync (m16n8k16 f16->f32)
// CTA: 128 threads (4 warps 2x2), tile M=128 co x N=112 spatial
// Warp tile 64(M) x 56(N); K loop 676 iters, 3-stage cp.async pipeline,
// one barrier per iter; BOTH A and B fragments register-double-buffered
// across kk (all LDSM for kk+1 issued before the 28-MMA stream of kk).
// grid = (448, 2)
// ---------------------------------------------------------------------------
#define A_BYTES     16384          // 128 rows x 128B
#define B_BYTES     14336          // 112 rows x 128B
#define STAGE_BYTES (A_BYTES + B_BYTES)     // 30720
#define NSTAGE      3
#define SMEM_DYN    (NSTAGE * STAGE_BYTES + 1024)

__global__ void __launch_bounds__(128, 2) conv_main_kernel(
    const float* __restrict__ gamma, const float* __restrict__ beta,
    const float* __restrict__ rmean, const float* __restrict__ rvar,
    float* __restrict__ out)
{
    extern __shared__ char smem_raw[];
    const uint32_t base = (smem_u32(smem_raw) + 1023u) & ~1023u;

    const int tid = threadIdx.x;
    const int l   = tid & 31;
    const int wid = tid >> 5;
    const int st  = blockIdx.x;
    const int cob = blockIdx.y;
    const int n   = st / 28;
    const int h0  = (st % 28) * 2;

    // ---- cp.async geometry: 8x16B chunks per 128B row; 128 thr = 16 rows/pass
    const int c16  = tid & 7;
    const int row0 = tid >> 3;                 // 0..15
    const char* a_base = (const char*)g_wt
        + (size_t)(cob * 128 + row0) * (CI * 2) + c16 * 16;
    const uint32_t a_dst0 = swz((uint32_t)(row0 * 128 + c16 * 16));
    const char* b_base = (const char*)g_xp
        + (size_t)(n * HP + h0) * WPAD * (CI * 2) + c16 * 16;
    uint32_t b_off[7];
    #pragma unroll
    for (int i = 0; i < 7; ++i) {
        const int rj = row0 + 16 * i;
        const int jr = (rj >= 56);
        b_off[i] = (uint32_t)(rj + jr * (WPAD - 56)) * (CI * 2);
    }
    const uint32_t b_dst0 = swz((uint32_t)(row0 * 128 + c16 * 16)) + A_BYTES;

    // Producer counters (no division in loop)
    int p_kc = 0;
    size_t p_woff = 0;
    size_t p_xoff = 0;
    int p_s = 0;
    int p_ws = 0;

    auto issue = [&]() {
        const uint32_t sb = base + (uint32_t)p_ws * STAGE_BYTES;
        const char* asrc = a_base + p_woff + (size_t)p_kc * 128;
        const char* bsrc = b_base + p_xoff + (size_t)p_kc * 128;
        #pragma unroll
        for (int i = 0; i < 8; ++i)
            cp16(sb + a_dst0 + i * 2048u, asrc + (size_t)i * 16 * (CI * 2));
        #pragma unroll
        for (int i = 0; i < 7; ++i)
            cp16(sb + b_dst0 + i * 2048u, bsrc + b_off[i]);
        CP_COMMIT();
        if (++p_ws == NSTAGE) p_ws = 0;
        if (++p_kc == 4) {
            p_kc = 0;
            p_woff += (size_t)CO * CI * 2;
            if (++p_s == KTAP) { p_s = 0; p_xoff += (size_t)(WPAD - (KTAP - 1)) * CI * 2; }
            else               { p_xoff += (size_t)CI * 2; }
        }
    };

    // ---- MMA fragment geometry (warp grid 2x2, warp tile 64(M) x 56(N))
    const int wm = wid >> 1, wn = wid & 1;
    const int m0 = wm * 64, n0 = wn * 56;
    uint32_t arow[4], axor[4];
    int brow[3]; uint32_t bxor[3];
    const uint32_t hi_a = (uint32_t)((l >> 4) << 4);
    const uint32_t hi_b = (uint32_t)(((l >> 3) & 1) << 4);
    #pragma unroll
    for (int mt = 0; mt < 4; ++mt) {
        const int r = m0 + 16 * mt + (l & 15);
        arow[mt] = (uint32_t)(r * 128);
        axor[mt] = (uint32_t)((r & 7) << 4);
    }
    #pragma unroll
    for (int bt = 0; bt < 3; ++bt) {
        const int r = n0 + 16 * bt + (l & 7) + ((l >> 4) << 3);
        brow[bt] = r; bxor[bt] = (uint32_t)((r & 7) << 4);
    }
    const int lm = l & 15;
    const int trow = n0 + 48 + (lm & 7);
    const uint32_t txor = (uint32_t)((trow & 7) << 4);
    const uint32_t thi  = (uint32_t)(((lm >> 3) & 1) << 4);

    float acc[4][7][4];
    #pragma unroll
    for (int i = 0; i < 4; ++i)
        #pragma unroll
        for (int j = 0; j < 7; ++j)
            #pragma unroll
            for (int k = 0; k < 4; ++k) acc[i][j][k] = 0.f;

    auto load_frags = [&](uint32_t ab, uint32_t bb, int kk,
                          uint32_t (*a)[4], uint32_t (*b)[4], uint32_t* bt2) {
        const uint32_t ka = (uint32_t)kk * 32;
        #pragma unroll
        for (int mt = 0; mt < 4; ++mt)
            ldsm4(a[mt], ab + arow[mt] + ((ka + hi_a) ^ axor[mt]));
        #pragma unroll
        for (int bt = 0; bt < 3; ++bt)
            ldsm4(b[bt], bb + brow[bt] * 128 + ((ka + hi_b) ^ bxor[bt]));
        ldsm2(bt2, bb + trow * 128 + ((ka + thi) ^ txor));
    };

    auto compute = [&](int stage) {
        const uint32_t ab = base + (uint32_t)stage * STAGE_BYTES;
        const uint32_t bb = ab + A_BYTES;
        uint32_t a[2][4][4], b[2][3][4], t2[2][2];
        load_frags(ab, bb, 0, a[0], b[0], t2[0]);
        #pragma unroll
        for (int kk = 0; kk < 4; ++kk) {
            const int cur = kk & 1;
            if (kk < 3)
                load_frags(ab, bb, kk + 1, a[cur ^ 1], b[cur ^ 1], t2[cur ^ 1]);
            #pragma unroll
            for (int bt = 0; bt < 3; ++bt) {
                #pragma unroll
                for (int mt = 0; mt < 4; ++mt) {
                    mma16816(acc[mt][2 * bt],     a[cur][mt], b[cur][bt]);
                    mma16816(acc[mt][2 * bt + 1], a[cur][mt], b[cur][bt] + 2);
                }
            }
            #pragma unroll
            for (int mt = 0; mt < 4; ++mt)
                mma16816(acc[mt][6], a[cur][mt], t2[cur]);
        }
    };

    // ---- mainloop: 676 K-stages, 3-stage pipeline, one barrier per iter.
    issue();   // stage 0
    issue();   // stage 1
    int rs = 0;
    #pragma unroll 1
    for (int i = 0; i < 674; ++i) {
        CP_WAIT(1);
        __syncthreads();
        issue();                   // iter i+2 -> stage (i+2)%3
        compute(rs);
        if (++rs == NSTAGE) rs = 0;
    }
    CP_WAIT(0);
    __syncthreads();
    compute(rs); if (++rs == NSTAGE) rs = 0;
    compute(rs);

    // ---- epilogue: BN + SiLU, registers -> NCHW fp32 (all lanes valid)
    const int h = h0 + wn;
    #pragma unroll
    for (int mt = 0; mt < 4; ++mt) {
        #pragma unroll
        for (int hf = 0; hf < 2; ++hf) {
            const int co = cob * 128 + m0 + 16 * mt + 8 * hf + (l >> 2);
            const float sc = gamma[co] * rsqrtf(rvar[co] + 1e-5f);
            const float sh = beta[co] - rmean[co] * sc;
            float* op = out + ((size_t)(n * CO + co) * HW + h) * HW;
            #pragma unroll
            for (int nt = 0; nt < 7; ++nt) {
                #pragma unroll
                for (int e = 0; e < 2; ++e) {
                    const int w = 8 * nt + 2 * (l & 3) + e;
                    const float y = acc[mt][nt][hf * 2 + e] * sc + sh;
                    op[w] = y / (1.f + __expf(-y));
                }
            }
        }
    }
}

// ---------------------------------------------------------------------------
// kernel_launch
// ---------------------------------------------------------------------------
extern "C" void kernel_launch(void* const* d_in, const int* in_sizes, int n_in,
                              void* d_out, int out_size)
{
    const float* x     = (const float*)d_in[0];
    const float* w     = (const float*)d_in[1];
    const float* gamma = (const float*)d_in[2];
    const float* beta  = (const float*)d_in[3];
    const float* rmean = (const float*)d_in[4];
    const float* rvar  = (const float*)d_in[5];
    float* out = (float*)d_out;

    cudaFuncSetAttribute(conv_main_kernel,
                         cudaFuncAttributeMaxDynamicSharedMemorySize, SMEM_DYN);

    prep_kernel<<<PAD_BLOCKS + WT_BLOCKS, 256>>>(x, w);
    conv_main_kernel<<<dim3(N_IMG * 28, 2), 128, SMEM_DYN>>>(gamma, beta, rmean, rvar, out);
}